// round 2
// baseline (speedup 1.0000x reference)
#include <cuda_runtime.h>
#include <cuda_bf16.h>

#define DIM 100            // DIM_E == DIM_R == 100
#define MAX_BATCH 8192
#define THREADS 256
#define N_ENT 500000
#define N_REL 1000

// Scratch: per-triple hinge values (deterministic two-stage reduction).
__device__ float g_scores[MAX_BATCH];

__device__ __forceinline__ int clampi(int v, int lo, int hi) {
    return min(max(v, lo), hi);
}

// One block per triple index i; warps 0-3 score the positive triple,
// warps 4-7 the negative. Uses M@(h-t)+r identity: one matvec per triple.
__global__ __launch_bounds__(THREADS)
void transr_score_kernel(const int* __restrict__ pos,
                         const int* __restrict__ neg,
                         const float* __restrict__ ent,
                         const float* __restrict__ rel,
                         const float* __restrict__ M,
                         int n) {
    int i = blockIdx.x;
    if (i >= n) return;

    __shared__ __align__(16) float diff[2][DIM];   // h - t for pos, neg
    __shared__ float wsum[8];

    int tid  = threadIdx.x;
    int wid  = tid >> 5;
    int lane = tid & 31;

    // Triple indices (h, r, t) — int32 layout [i*3 + {0,1,2}].
    // Clamped defensively: a dtype surprise then shows as rel_err, not a crash.
    int hp = clampi(pos[i * 3 + 0], 0, N_ENT - 1);
    int rp = clampi(pos[i * 3 + 1], 0, N_REL - 1);
    int tp = clampi(pos[i * 3 + 2], 0, N_ENT - 1);
    int hn = clampi(neg[i * 3 + 0], 0, N_ENT - 1);
    int rn = clampi(neg[i * 3 + 1], 0, N_REL - 1);
    int tn = clampi(neg[i * 3 + 2], 0, N_ENT - 1);

    // Build diff vectors in shared: threads 0..99 -> pos, 128..227 -> neg.
    if (tid < DIM) {
        diff[0][tid] = __ldg(&ent[(long long)hp * DIM + tid]) -
                       __ldg(&ent[(long long)tp * DIM + tid]);
    } else if (tid >= 128 && tid < 128 + DIM) {
        int e = tid - 128;
        diff[1][e] = __ldg(&ent[(long long)hn * DIM + e]) -
                     __ldg(&ent[(long long)tn * DIM + e]);
    }
    __syncthreads();

    int side   = wid >> 2;        // 0 = pos, 1 = neg
    int wlocal = wid & 3;         // 0..3: which 25-row slab
    int r = side ? rn : rp;
    const float* __restrict__ Mr   = M   + (long long)r * (DIM * DIM);
    const float* __restrict__ relr = rel + r * DIM;

    // Each lane < 25 owns 4 consecutive elements of the diff vector
    // (loaded once; reused for all 25 rows).
    float d0 = 0.f, d1 = 0.f, d2 = 0.f, d3 = 0.f;
    if (lane < 25) {
        float4 dv = reinterpret_cast<const float4*>(diff[side])[lane];
        d0 = dv.x; d1 = dv.y; d2 = dv.z; d3 = dv.w;
    }

    float acc = 0.f;
    #pragma unroll
    for (int k = 0; k < 25; ++k) {
        int row = wlocal * 25 + k;
        float p = 0.f;
        if (lane < 25) {
            // Row stride = 400 B (16B-aligned) -> clean LDG.128
            float4 m = reinterpret_cast<const float4*>(Mr + row * DIM)[lane];
            p = fmaf(m.x, d0, fmaf(m.y, d1, fmaf(m.z, d2, m.w * d3)));
        }
        // Full-warp tree reduce (lanes 25..31 contribute 0)
        #pragma unroll
        for (int s = 16; s > 0; s >>= 1)
            p += __shfl_down_sync(0xffffffffu, p, s);
        if (lane == 0)
            acc += fabsf(p + __ldg(&relr[row]));
    }

    if (lane == 0) wsum[wid] = acc;
    __syncthreads();

    if (tid == 0) {
        float pv = wsum[0] + wsum[1] + wsum[2] + wsum[3];
        float nv = wsum[4] + wsum[5] + wsum[6] + wsum[7];
        g_scores[i] = fmaxf(0.f, pv - nv + 1.0f);   // MARGIN = 1.0
    }
}

// Deterministic single-block mean reduction of g_scores[0..n)
__global__ __launch_bounds__(THREADS)
void transr_reduce_kernel(float* __restrict__ out, int n) {
    __shared__ float s[THREADS];
    float a = 0.f;
    for (int j = threadIdx.x; j < n; j += THREADS)
        a += g_scores[j];
    s[threadIdx.x] = a;
    __syncthreads();
    #pragma unroll
    for (int stride = THREADS / 2; stride > 0; stride >>= 1) {
        if (threadIdx.x < stride) s[threadIdx.x] += s[threadIdx.x + stride];
        __syncthreads();
    }
    if (threadIdx.x == 0) out[0] = s[0] / (float)n;
}

extern "C" void kernel_launch(void* const* d_in, const int* in_sizes, int n_in,
                              void* d_out, int out_size) {
    const int*   pos = (const int*)d_in[0];
    const int*   neg = (const int*)d_in[1];
    const float* ent = (const float*)d_in[2];
    const float* rel = (const float*)d_in[3];
    const float* M   = (const float*)d_in[4];
    float* out = (float*)d_out;

    int n = in_sizes[0] / 3;           // BATCH (8192)
    if (n > MAX_BATCH) n = MAX_BATCH;

    transr_score_kernel<<<n, THREADS>>>(pos, neg, ent, rel, M, n);
    transr_reduce_kernel<<<1, THREADS>>>(out, n);
}

// round 3
// speedup vs baseline: 1.3511x; 1.3511x over previous
#include <cuda_runtime.h>
#include <cuda_bf16.h>

#define DIM 100
#define NREL 1000
#define BATCH 8192
#define NITEMS (2 * BATCH)       // pos items [0,8192), neg items [8192,16384)
#define N_ENT 500000

// ---- device scratch (no allocations allowed) ----
__device__ float g_diff[NITEMS * DIM];   // per-item (h - t), 6.55 MB
__device__ int   g_count[NREL];
__device__ int   g_offset[NREL];
__device__ int   g_cursor[NREL];
__device__ int   g_items[NITEMS];
__device__ float g_score[NITEMS];        // per-item sum |M(h-t)+r|

__device__ __forceinline__ int clampi(int v, int lo, int hi) {
    return min(max(v, lo), hi);
}

// Fetch triple (h,r,t) for flat item id (pos first, then neg), clamped.
__device__ __forceinline__ void get_triple(const int* __restrict__ pos,
                                           const int* __restrict__ neg,
                                           int item, int& h, int& r, int& t) {
    const int* trip = (item < BATCH) ? (pos + item * 3) : (neg + (item - BATCH) * 3);
    h = clampi(trip[0], 0, N_ENT - 1);
    r = clampi(trip[1], 0, NREL - 1);
    t = clampi(trip[2], 0, N_ENT - 1);
}

// K0: zero relation counters
__global__ void k_zero() {
    int i = blockIdx.x * blockDim.x + threadIdx.x;
    if (i < NREL) g_count[i] = 0;
}

// K1: one warp per item — gather diff = ent[h]-ent[t] into g_diff, histogram r.
__global__ __launch_bounds__(256)
void k_diff_hist(const int* __restrict__ pos, const int* __restrict__ neg,
                 const float* __restrict__ ent) {
    int warp = (blockIdx.x * blockDim.x + threadIdx.x) >> 5;
    int lane = threadIdx.x & 31;
    if (warp >= NITEMS) return;
    int h, r, t;
    get_triple(pos, neg, warp, h, r, t);
    if (lane < 25) {
        const float4* hp = reinterpret_cast<const float4*>(ent + (long long)h * DIM);
        const float4* tp = reinterpret_cast<const float4*>(ent + (long long)t * DIM);
        float4 a = __ldg(hp + lane), b = __ldg(tp + lane);
        float4 d = make_float4(a.x - b.x, a.y - b.y, a.z - b.z, a.w - b.w);
        reinterpret_cast<float4*>(g_diff + (long long)warp * DIM)[lane] = d;
    }
    if (lane == 0) atomicAdd(&g_count[r], 1);
}

// K2: exclusive scan of counts (single block, Hillis-Steele)
__global__ __launch_bounds__(1024)
void k_scan() {
    __shared__ int s[1024];
    int tid = threadIdx.x;
    int c = (tid < NREL) ? g_count[tid] : 0;
    s[tid] = c;
    __syncthreads();
    #pragma unroll
    for (int d = 1; d < 1024; d <<= 1) {
        int v = (tid >= d) ? s[tid - d] : 0;
        __syncthreads();
        s[tid] += v;
        __syncthreads();
    }
    if (tid < NREL) {
        int excl = s[tid] - c;
        g_offset[tid] = excl;
        g_cursor[tid] = excl;
    }
}

// K3: scatter item ids into relation-sorted order
__global__ __launch_bounds__(256)
void k_scatter(const int* __restrict__ pos, const int* __restrict__ neg) {
    int item = blockIdx.x * blockDim.x + threadIdx.x;
    if (item >= NITEMS) return;
    int h, r, t;
    get_triple(pos, neg, item, h, r, t);
    int slot = atomicAdd(&g_cursor[r], 1);
    g_items[slot] = item;
}

// K4: one CTA per relation. M loaded+transposed once into smem, reused for
// all items of that relation, 8 items per inner pass.
#define MT_STRIDE 101   // gcd(101,32)=1 -> conflict-free columns
#define GITEMS 8
__global__ __launch_bounds__(128)
void k_gemm(const float* __restrict__ rel, const float* __restrict__ M) {
    __shared__ float Mt[DIM * MT_STRIDE];     // Mt[k*101 + j] = M[j][k], 40.4 KB
    __shared__ float ds[GITEMS][DIM];         // diff vectors for current group
    __shared__ float relrow[DIM];
    __shared__ int   itm[GITEMS];
    __shared__ float wred[4][GITEMS];

    int r = blockIdx.x;
    int cnt = g_count[r];
    if (cnt == 0) return;
    int base = g_offset[r];
    int tid  = threadIdx.x;
    int wid  = tid >> 5;
    int lane = tid & 31;

    if (tid < DIM) relrow[tid] = __ldg(&rel[r * DIM + tid]);
    const float* Mr = M + (long long)r * (DIM * DIM);
    for (int idx = tid; idx < DIM * DIM; idx += 128) {
        int row = idx / DIM, col = idx - row * DIM;
        Mt[col * MT_STRIDE + row] = __ldg(&Mr[idx]);
    }
    __syncthreads();

    for (int g = 0; g < cnt; g += GITEMS) {
        int nit = min(GITEMS, cnt - g);
        if (tid < GITEMS) itm[tid] = (tid < nit) ? g_items[base + g + tid] : 0;
        __syncthreads();
        for (int idx = tid; idx < GITEMS * DIM; idx += 128) {
            int it = idx / DIM, k = idx - it * DIM;
            ds[it][k] = (it < nit) ? g_diff[(long long)itm[it] * DIM + k] : 0.f;
        }
        __syncthreads();

        int j = tid;                       // output row owned by this thread
        float acc[GITEMS];
        #pragma unroll
        for (int it = 0; it < GITEMS; ++it) acc[it] = (j < DIM) ? relrow[j] : 0.f;

        if (j < DIM) {
            #pragma unroll 5
            for (int k = 0; k < DIM; k += 4) {
                float m0 = Mt[(k + 0) * MT_STRIDE + j];
                float m1 = Mt[(k + 1) * MT_STRIDE + j];
                float m2 = Mt[(k + 2) * MT_STRIDE + j];
                float m3 = Mt[(k + 3) * MT_STRIDE + j];
                #pragma unroll
                for (int it = 0; it < GITEMS; ++it) {
                    float4 dv = *reinterpret_cast<const float4*>(&ds[it][k]);
                    acc[it] = fmaf(m0, dv.x, acc[it]);
                    acc[it] = fmaf(m1, dv.y, acc[it]);
                    acc[it] = fmaf(m2, dv.z, acc[it]);
                    acc[it] = fmaf(m3, dv.w, acc[it]);
                }
            }
        }

        // per-item abs-sum across j (all 128 threads participate; j>=100 -> 0)
        #pragma unroll
        for (int it = 0; it < GITEMS; ++it) {
            float v = (j < DIM) ? fabsf(acc[it]) : 0.f;
            #pragma unroll
            for (int s = 16; s > 0; s >>= 1)
                v += __shfl_down_sync(0xffffffffu, v, s);
            if (lane == 0) wred[wid][it] = v;
        }
        __syncthreads();
        if (tid < nit)
            g_score[itm[tid]] = wred[0][tid] + wred[1][tid] + wred[2][tid] + wred[3][tid];
        __syncthreads();
    }
}

// K5: mean hinge over the batch (deterministic single block)
__global__ __launch_bounds__(256)
void k_final(float* __restrict__ out) {
    __shared__ float s[256];
    float a = 0.f;
    for (int i = threadIdx.x; i < BATCH; i += 256)
        a += fmaxf(0.f, g_score[i] - g_score[i + BATCH] + 1.0f);
    s[threadIdx.x] = a;
    __syncthreads();
    #pragma unroll
    for (int st = 128; st > 0; st >>= 1) {
        if (threadIdx.x < st) s[threadIdx.x] += s[threadIdx.x + st];
        __syncthreads();
    }
    if (threadIdx.x == 0) out[0] = s[0] / (float)BATCH;
}

extern "C" void kernel_launch(void* const* d_in, const int* in_sizes, int n_in,
                              void* d_out, int out_size) {
    const int*   pos = (const int*)d_in[0];
    const int*   neg = (const int*)d_in[1];
    const float* ent = (const float*)d_in[2];
    const float* rel = (const float*)d_in[3];
    const float* M   = (const float*)d_in[4];
    float* out = (float*)d_out;

    k_zero<<<(NREL + 255) / 256, 256>>>();
    k_diff_hist<<<(NITEMS * 32 + 255) / 256, 256>>>(pos, neg, ent);
    k_scan<<<1, 1024>>>();
    k_scatter<<<(NITEMS + 255) / 256, 256>>>(pos, neg);
    k_gemm<<<NREL, 128>>>(rel, M);
    k_final<<<1, 256>>>(out);
}